// round 8
// baseline (speedup 1.0000x reference)
#include <cuda_runtime.h>
#include <cstdint>

// ============================================================================
// StagePolicyNetwork: gather -> [208x128] tf32 mma.sync GEMM -> relu
// -> [128x64] GEMM -> relu -> [64x1] dot.
// Persistent CTAs, 512 threads = TWO independent 256-thread tile pipelines
// (named barriers), 64-row tiles, 4-deep cp.async ring, cross-tile pipelining.
// compute_103-safe (no tcgen05).
// ============================================================================

__device__ __forceinline__ uint32_t smem_u32(const void* p) {
    uint32_t a;
    asm("{ .reg .u64 t; cvta.to.shared.u64 t, %1; cvt.u32.u64 %0, t; }" : "=r"(a) : "l"(p));
    return a;
}
__device__ __forceinline__ uint32_t f2tf(float f) {
    uint32_t u; asm("cvt.rna.tf32.f32 %0, %1;" : "=r"(u) : "f"(f)); return u;
}
__device__ __forceinline__ void cp16(uint32_t saddr, const void* gaddr) {
    asm volatile("cp.async.cg.shared.global [%0], [%1], 16;" :: "r"(saddr), "l"(gaddr));
}
__device__ __forceinline__ void cp_commit() {
    asm volatile("cp.async.commit_group;" ::: "memory");
}
template <int N>
__device__ __forceinline__ void cp_wait() {
    asm volatile("cp.async.wait_group %0;" :: "n"(N) : "memory");
}
__device__ __forceinline__ void hbar(int barid) {
    asm volatile("bar.sync %0, 256;" :: "r"(barid) : "memory");
}
__device__ __forceinline__ void mma_tf32(float& c0, float& c1, float& c2, float& c3,
                                         uint32_t a0, uint32_t a1, uint32_t a2, uint32_t a3,
                                         uint32_t b0, uint32_t b1) {
    asm volatile(
        "mma.sync.aligned.m16n8k8.row.col.f32.tf32.tf32.f32 "
        "{%0,%1,%2,%3}, {%4,%5,%6,%7}, {%8,%9}, {%0,%1,%2,%3};"
        : "+f"(c0), "+f"(c1), "+f"(c2), "+f"(c3)
        : "r"(a0), "r"(a1), "r"(a2), "r"(a3), "r"(b0), "r"(b1));
}

// ---------------- constants --------------------------------------------------
static constexpr int TILE = 64;         // rows per half-pipeline tile
static constexpr int KK1 = 26;          // 208 / 8
static constexpr int KK2 = 16;          // 128 / 8
static constexpr int NCH = 7;           // chunks of 32 cols; last has 2 kk

// SMEM layout (bytes)
static constexpr int SM_W1F  = 0;                      // 26*16*32*8 = 106496
static constexpr int SM_W2F  = 106496;                 // 16*8*32*8  = 32768
static constexpr int SM_H0   = 139264;                 // 32 KB (half 0: H / A ring)
static constexpr int SM_H1   = 172032;                 // 32 KB (half 1)
static constexpr int SM_B1   = 204800;                 // 512
static constexpr int SM_B2   = 205312;                 // 256
static constexpr int SM_W3   = 205568;                 // 256
static constexpr int SM_PT0  = 205824;                 // 64*4*4 = 1024
static constexpr int SM_PT1  = 206848;                 // 1024
static constexpr int SM_CUM  = 207872;                 // 80
static constexpr int SMEM_TOTAL = 208000;

__global__ __launch_bounds__(512, 1)
void stage_policy_kernel(
    const float* __restrict__ x, const float* __restrict__ hn,
    const float* __restrict__ hd, const float* __restrict__ hg,
    const float* __restrict__ W1g, const float* __restrict__ b1g,
    const float* __restrict__ W2g, const float* __restrict__ b2g,
    const float* __restrict__ W3g, const float* __restrict__ b3g,
    const int* __restrict__ stage_idx, const int* __restrict__ batch,
    const int* __restrict__ nsa,
    float* __restrict__ out, int M, int G, int ntiles)
{
    extern __shared__ char smem[];
    const uint32_t sb = smem_u32(smem);
    const int tid  = threadIdx.x;
    const int lane = tid & 31;
    const int g4   = lane >> 2;         // row within 8
    const int t4   = lane & 3;          // col pair
    const int halfid = tid >> 8;        // 0: warps 0-7, 1: warps 8-15
    const int htid = tid & 255;
    const int hwid = (tid >> 5) & 7;
    const int mg   = hwid >> 2;         // rows 32*mg .. +32 (of 64)
    const int ng   = hwid & 3;          // L1 cols 32*ng, L2 cols 16*ng
    const int barid = 1 + halfid;

    const int HB = halfid ? SM_H1 : SM_H0;
    float* sB1  = (float*)(smem + SM_B1);
    float* sB2  = (float*)(smem + SM_B2);
    float* sW3  = (float*)(smem + SM_W3);
    float* sPt  = (float*)(smem + (halfid ? SM_PT1 : SM_PT0));
    int*   sCum = (int*)(smem + SM_CUM);

    // ---------------- one-time fills (whole CTA) ----------------
    for (int i = tid; i < KK1 * 16 * 32; i += 512) {
        int l = i & 31, n = (i >> 5) & 15, kk = i >> 9;
        int k0 = kk * 8 + (l & 3), col = n * 8 + (l >> 2);
        uint2 v;
        v.x = f2tf(W1g[k0 * 128 + col]);
        v.y = f2tf(W1g[(k0 + 4) * 128 + col]);
        ((uint2*)(smem + SM_W1F))[i] = v;
    }
    for (int i = tid; i < KK2 * 8 * 32; i += 512) {
        int l = i & 31, n = (i >> 5) & 7, kk = i >> 8;
        int k0 = kk * 8 + (l & 3), col = n * 8 + (l >> 2);
        uint2 v;
        v.x = f2tf(W2g[k0 * 64 + col]);
        v.y = f2tf(W2g[(k0 + 4) * 64 + col]);
        ((uint2*)(smem + SM_W2F))[i] = v;
    }
    if (tid < 128) sB1[tid] = b1g[tid];
    if (tid >= 128 && tid < 192) sB2[tid - 128] = b2g[tid - 128];
    if (tid >= 192 && tid < 256) sW3[tid - 192] = W3g[tid - 192];
    if (tid == 0) {
        int c = 0; sCum[0] = 0;
        for (int i = 0; i < G; i++) { c += nsa[i]; sCum[i + 1] = c; }
    }
    const float b3v = b3g[0];
    __syncthreads();

    // gather role within half: 4 threads per row
    const int grow = htid >> 2;         // 0..63
    const int q    = htid & 3;          // kk within chunk (8 cols)
    const uint32_t dbase = sb + HB + (uint32_t)q * 2048u
                           + (uint32_t)(grow >> 4) * 512u
                           + (uint32_t)((grow >> 3) & 1) * 128u
                           + (uint32_t)(grow & 7) * 16u;

    const int tstride = 2 * gridDim.x;
    const int tile0   = 2 * blockIdx.x + halfid;

    // carried source pointers for this thread's row
    const float *cpx, *cphn, *cphd, *cphg;
    {
        const int gr0 = tile0 * TILE + grow;
        const int grc = (gr0 < M) ? ((gr0 < 0) ? 0 : gr0) : (M - 1);
        const int ci = stage_idx[grc];
        const int cb = batch[ci];
        int cg = 0;
        #pragma unroll 1
        while (cg + 1 < G && grc >= sCum[cg + 1]) cg++;
        cpx  = x  + (size_t)ci * 16;
        cphn = hn + (size_t)ci * 64;
        cphd = hd + (size_t)cb * 64;
        cphg = hg + (size_t)cg * 64;
    }

    auto issue = [&](int c, const float* px, const float* phn,
                     const float* phd, const float* phg) {
        const int col0 = 32 * c + 8 * q;
        if (col0 < 208) {
            const float* p;
            if      (col0 < 16)  p = px  + col0;
            else if (col0 < 80)  p = phn + (col0 - 16);
            else if (col0 < 144) p = phd + (col0 - 80);
            else                 p = phg + (col0 - 144);
            const uint32_t d = dbase + (uint32_t)(c & 3) * 8192u;
            cp16(d,        p);
            cp16(d + 256u, p + 4);
        }
        cp_commit();
    };

    if (tile0 < ntiles) {
        issue(0, cpx, cphn, cphd, cphg);
        issue(1, cpx, cphn, cphd, cphg);
        issue(2, cpx, cphn, cphd, cphg);
    }

    for (int tile = tile0; tile < ntiles; tile += tstride) {
        int nidx = 0, ngr = 0;
        const int tn = tile + tstride;
        const bool hasnext = (tn < ntiles);

        float acc[2][4][4];
        #pragma unroll
        for (int a = 0; a < 2; a++)
            #pragma unroll
            for (int b = 0; b < 4; b++)
                #pragma unroll
                for (int w = 0; w < 4; w++) acc[a][b][w] = 0.f;

        // ---------------- layer 1: 7 chunks, 4-buffer ring, 1 barrier/chunk --
        #pragma unroll
        for (int c = 0; c < NCH; c++) {
            if      (c <= 4) cp_wait<2>();
            else if (c == 5) cp_wait<1>();
            else             cp_wait<0>();
            hbar(barid);

            const char* ab = smem + HB + (c & 3) * 8192;
            const int kkmax = (c == NCH - 1) ? 2 : 4;
            #pragma unroll
            for (int kk = 0; kk < 4; kk++) {
                if (kk >= kkmax) break;
                uint32_t a[2][4];
                #pragma unroll
                for (int ml = 0; ml < 2; ml++) {
                    const uint32_t* ap =
                        (const uint32_t*)(ab + (kk * 4 + 2 * mg + ml) * 512) + lane;
                    a[ml][0] = ap[0];  a[ml][1] = ap[32];
                    a[ml][2] = ap[64]; a[ml][3] = ap[96];
                }
                const int kkg = 4 * c + kk;
                uint2 bf[4];
                #pragma unroll
                for (int nl = 0; nl < 4; nl++)
                    bf[nl] = ((const uint2*)(smem + SM_W1F))[(kkg * 16 + 4 * ng + nl) * 32 + lane];
                #pragma unroll
                for (int ml = 0; ml < 2; ml++)
                    #pragma unroll
                    for (int nl = 0; nl < 4; nl++)
                        mma_tf32(acc[ml][nl][0], acc[ml][nl][1], acc[ml][nl][2], acc[ml][nl][3],
                                 a[ml][0], a[ml][1], a[ml][2], a[ml][3],
                                 bf[nl].x, bf[nl].y);
            }
            if (c + 3 < NCH) issue(c + 3, cpx, cphn, cphd, cphg);
            if (c == 0) {
                const int te = hasnext ? tn : tile;
                const int g0 = te * TILE + grow;
                ngr  = (g0 < M) ? g0 : (M - 1);
                nidx = stage_idx[ngr];
            }
        }
        hbar(barid);   // all warps done reading A ring before H writes

        const int nbd = batch[nidx];

        // ---------------- epilogue 1: +b1, relu, tf32 -> H (fragment-major) --
        #pragma unroll
        for (int ml = 0; ml < 2; ml++) {
            #pragma unroll
            for (int nl = 0; nl < 4; nl++) {
                const int col0 = 32 * ng + 8 * nl + 2 * t4;
                const float2 bb = *(const float2*)(sB1 + col0);
                uint2 lo, hi;
                lo.x = f2tf(fmaxf(acc[ml][nl][0] + bb.x, 0.f));
                lo.y = f2tf(fmaxf(acc[ml][nl][1] + bb.y, 0.f));
                hi.x = f2tf(fmaxf(acc[ml][nl][2] + bb.x, 0.f));
                hi.y = f2tf(fmaxf(acc[ml][nl][3] + bb.y, 0.f));
                const int kk2 = 4 * ng + nl;
                const int m2  = 2 * mg + ml;
                const int reg = 2 * (t4 >> 1);
                const int ln2 = g4 * 4 + 2 * (t4 & 1);
                char* hp = smem + HB + ((kk2 * 4 + m2) * 4 + reg) * 128 + ln2 * 4;
                *(uint2*)(hp)       = lo;   // rows g4    (c0,c1)
                *(uint2*)(hp + 128) = hi;   // rows g4+8  (c2,c3)
            }
        }
        int ngg = 0;
        #pragma unroll 1
        while (ngg + 1 < G && ngr >= sCum[ngg + 1]) ngg++;
        hbar(barid);

        // ---------------- layer 2 ----------------
        float ac2[2][2][4];
        #pragma unroll
        for (int a = 0; a < 2; a++)
            #pragma unroll
            for (int b = 0; b < 2; b++)
                #pragma unroll
                for (int w = 0; w < 4; w++) ac2[a][b][w] = 0.f;

        #pragma unroll 4
        for (int kk = 0; kk < KK2; kk++) {
            uint32_t a[2][4];
            #pragma unroll
            for (int ml = 0; ml < 2; ml++) {
                const uint32_t* ap =
                    (const uint32_t*)(smem + HB + (kk * 4 + 2 * mg + ml) * 512) + lane;
                a[ml][0] = ap[0];  a[ml][1] = ap[32];
                a[ml][2] = ap[64]; a[ml][3] = ap[96];
            }
            uint2 bf[2];
            #pragma unroll
            for (int nl = 0; nl < 2; nl++)
                bf[nl] = ((const uint2*)(smem + SM_W2F))[(kk * 8 + 2 * ng + nl) * 32 + lane];
            #pragma unroll
            for (int ml = 0; ml < 2; ml++)
                #pragma unroll
                for (int nl = 0; nl < 2; nl++)
                    mma_tf32(ac2[ml][nl][0], ac2[ml][nl][1], ac2[ml][nl][2], ac2[ml][nl][3],
                             a[ml][0], a[ml][1], a[ml][2], a[ml][3],
                             bf[nl].x, bf[nl].y);
        }

        // ---------------- epilogue 2: +b2, relu, dot W3, reduce --------------
        #pragma unroll
        for (int ml = 0; ml < 2; ml++) {
            float p0 = 0.f, p1 = 0.f;
            #pragma unroll
            for (int nl = 0; nl < 2; nl++) {
                const int col0 = 16 * ng + 8 * nl + 2 * t4;
                const float2 bb = *(const float2*)(sB2 + col0);
                const float2 ww = *(const float2*)(sW3 + col0);
                p0 += fmaxf(ac2[ml][nl][0] + bb.x, 0.f) * ww.x
                    + fmaxf(ac2[ml][nl][1] + bb.y, 0.f) * ww.y;
                p1 += fmaxf(ac2[ml][nl][2] + bb.x, 0.f) * ww.x
                    + fmaxf(ac2[ml][nl][3] + bb.y, 0.f) * ww.y;
            }
            p0 += __shfl_xor_sync(0xffffffffu, p0, 1);
            p0 += __shfl_xor_sync(0xffffffffu, p0, 2);
            p1 += __shfl_xor_sync(0xffffffffu, p1, 1);
            p1 += __shfl_xor_sync(0xffffffffu, p1, 2);
            if (t4 == 0) {
                const int r0 = 32 * mg + 16 * ml + g4;
                sPt[r0 * 4 + ng]       = p0;
                sPt[(r0 + 8) * 4 + ng] = p1;
            }
        }
        hbar(barid);

        // out write + carry + cross-tile issues (H fully dead now)
        const int nbidx2 = nidx;
        cpx  = x  + (size_t)nbidx2 * 16;
        cphn = hn + (size_t)nbidx2 * 64;
        cphd = hd + (size_t)nbd * 64;
        cphg = hg + (size_t)ngg * 64;
        if (hasnext) {
            issue(0, cpx, cphn, cphd, cphg);
            issue(1, cpx, cphn, cphd, cphg);
            issue(2, cpx, cphn, cphd, cphg);
        }
        if (htid < 64) {
            const float4 p = ((const float4*)sPt)[htid];
            const int go = tile * TILE + htid;
            if (go < M) out[go] = p.x + p.y + p.z + p.w + b3v;
        }
    }
}

// ---------------------------------------------------------------------------
extern "C" void kernel_launch(void* const* d_in, const int* in_sizes, int n_in,
                              void* d_out, int out_size) {
    const float* x   = (const float*)d_in[0];
    const float* hn  = (const float*)d_in[1];
    const float* hd  = (const float*)d_in[2];
    const float* hg  = (const float*)d_in[3];
    const float* W1  = (const float*)d_in[4];
    const float* b1  = (const float*)d_in[5];
    const float* W2  = (const float*)d_in[6];
    const float* b2  = (const float*)d_in[7];
    const float* W3  = (const float*)d_in[8];
    const float* b3  = (const float*)d_in[9];
    const int* sidx  = (const int*)d_in[10];
    const int* batch = (const int*)d_in[11];
    const int* nsa   = (const int*)d_in[12];
    float* out = (float*)d_out;

    const int M = in_sizes[10];
    const int G = in_sizes[12];
    const int ntiles = (M + TILE - 1) / TILE;

    static int sms = 0;
    if (sms == 0) {
        cudaDeviceGetAttribute(&sms, cudaDevAttrMultiProcessorCount, 0);
        cudaFuncSetAttribute(stage_policy_kernel,
                             cudaFuncAttributeMaxDynamicSharedMemorySize, SMEM_TOTAL);
        if (sms <= 0) sms = 148;
    }
    const int half_tiles = (ntiles + 1) / 2;
    const int grid = (half_tiles < sms) ? half_tiles : sms;

    stage_policy_kernel<<<grid, 512, SMEM_TOTAL>>>(
        x, hn, hd, hg, W1, b1, W2, b2, W3, b3, sidx, batch, nsa, out, M, G, ntiles);
}

// round 9
// speedup vs baseline: 1.0117x; 1.0117x over previous
#include <cuda_runtime.h>
#include <cstdint>

// ============================================================================
// StagePolicyNetwork: gather -> [208x128] tf32 mma.sync GEMM -> relu
// -> [128x64] GEMM -> relu -> [64x1] dot.
// Persistent CTAs, 512 threads = TWO independent 256-thread tile pipelines
// (named barriers), 64-row tiles, 4-deep cp.async ring, cross-tile pipelining.
// compute_103-safe (no tcgen05).
// ============================================================================

__device__ __forceinline__ uint32_t smem_u32(const void* p) {
    uint32_t a;
    asm("{ .reg .u64 t; cvta.to.shared.u64 t, %1; cvt.u32.u64 %0, t; }" : "=r"(a) : "l"(p));
    return a;
}
__device__ __forceinline__ uint32_t f2tf(float f) {
    uint32_t u; asm("cvt.rna.tf32.f32 %0, %1;" : "=r"(u) : "f"(f)); return u;
}
__device__ __forceinline__ void cp16(uint32_t saddr, const void* gaddr) {
    asm volatile("cp.async.cg.shared.global [%0], [%1], 16;" :: "r"(saddr), "l"(gaddr));
}
__device__ __forceinline__ void cp_commit() {
    asm volatile("cp.async.commit_group;" ::: "memory");
}
template <int N>
__device__ __forceinline__ void cp_wait() {
    asm volatile("cp.async.wait_group %0;" :: "n"(N) : "memory");
}
__device__ __forceinline__ void hbar(int barid) {
    asm volatile("bar.sync %0, 256;" :: "r"(barid) : "memory");
}
__device__ __forceinline__ void mma_tf32(float& c0, float& c1, float& c2, float& c3,
                                         uint32_t a0, uint32_t a1, uint32_t a2, uint32_t a3,
                                         uint32_t b0, uint32_t b1) {
    asm volatile(
        "mma.sync.aligned.m16n8k8.row.col.f32.tf32.tf32.f32 "
        "{%0,%1,%2,%3}, {%4,%5,%6,%7}, {%8,%9}, {%0,%1,%2,%3};"
        : "+f"(c0), "+f"(c1), "+f"(c2), "+f"(c3)
        : "r"(a0), "r"(a1), "r"(a2), "r"(a3), "r"(b0), "r"(b1));
}

// ---------------- constants --------------------------------------------------
static constexpr int TILE = 64;         // rows per half-pipeline tile
static constexpr int KK1 = 26;          // 208 / 8
static constexpr int KK2 = 16;          // 128 / 8
static constexpr int NCH = 7;           // chunks of 32 cols; last has 2 kk

// SMEM layout (bytes)
static constexpr int SM_W1F  = 0;                      // 26*16*32*8 = 106496
static constexpr int SM_W2F  = 106496;                 // 16*8*32*8  = 32768
static constexpr int SM_H0   = 139264;                 // 32 KB (half 0: H / A ring)
static constexpr int SM_H1   = 172032;                 // 32 KB (half 1)
static constexpr int SM_B1   = 204800;                 // 512
static constexpr int SM_B2   = 205312;                 // 256
static constexpr int SM_W3   = 205568;                 // 256
static constexpr int SM_PT0  = 205824;                 // 64*4*4 = 1024
static constexpr int SM_PT1  = 206848;                 // 1024
static constexpr int SM_CUM  = 207872;                 // 80
static constexpr int SMEM_TOTAL = 208000;

__global__ __launch_bounds__(512, 1)
void stage_policy_kernel(
    const float* __restrict__ x, const float* __restrict__ hn,
    const float* __restrict__ hd, const float* __restrict__ hg,
    const float* __restrict__ W1g, const float* __restrict__ b1g,
    const float* __restrict__ W2g, const float* __restrict__ b2g,
    const float* __restrict__ W3g, const float* __restrict__ b3g,
    const int* __restrict__ stage_idx, const int* __restrict__ batch,
    const int* __restrict__ nsa,
    float* __restrict__ out, int M, int G, int ntiles)
{
    extern __shared__ char smem[];
    const uint32_t sb = smem_u32(smem);
    const int tid  = threadIdx.x;
    const int lane = tid & 31;
    const int g4   = lane >> 2;         // row within 8
    const int t4   = lane & 3;          // col pair
    const int halfid = tid >> 8;        // 0: warps 0-7, 1: warps 8-15
    const int htid = tid & 255;
    const int hwid = (tid >> 5) & 7;
    const int mg   = hwid >> 2;         // rows 32*mg .. +32 (of 64)
    const int ng   = hwid & 3;          // L1 cols 32*ng, L2 cols 16*ng
    const int barid = 1 + halfid;

    const int HB = halfid ? SM_H1 : SM_H0;
    float* sB1  = (float*)(smem + SM_B1);
    float* sB2  = (float*)(smem + SM_B2);
    float* sW3  = (float*)(smem + SM_W3);
    float* sPt  = (float*)(smem + (halfid ? SM_PT1 : SM_PT0));
    int*   sCum = (int*)(smem + SM_CUM);

    // ---------------- one-time fills (whole CTA) ----------------
    for (int i = tid; i < KK1 * 16 * 32; i += 512) {
        int l = i & 31, n = (i >> 5) & 15, kk = i >> 9;
        int k0 = kk * 8 + (l & 3), col = n * 8 + (l >> 2);
        uint2 v;
        v.x = f2tf(W1g[k0 * 128 + col]);
        v.y = f2tf(W1g[(k0 + 4) * 128 + col]);
        ((uint2*)(smem + SM_W1F))[i] = v;
    }
    for (int i = tid; i < KK2 * 8 * 32; i += 512) {
        int l = i & 31, n = (i >> 5) & 7, kk = i >> 8;
        int k0 = kk * 8 + (l & 3), col = n * 8 + (l >> 2);
        uint2 v;
        v.x = f2tf(W2g[k0 * 64 + col]);
        v.y = f2tf(W2g[(k0 + 4) * 64 + col]);
        ((uint2*)(smem + SM_W2F))[i] = v;
    }
    if (tid < 128) sB1[tid] = b1g[tid];
    if (tid >= 128 && tid < 192) sB2[tid - 128] = b2g[tid - 128];
    if (tid >= 192 && tid < 256) sW3[tid - 192] = W3g[tid - 192];
    if (tid == 0) {
        int c = 0; sCum[0] = 0;
        for (int i = 0; i < G; i++) { c += nsa[i]; sCum[i + 1] = c; }
    }
    const float b3v = b3g[0];
    __syncthreads();

    // gather role within half: 4 threads per row
    const int grow = htid >> 2;         // 0..63
    const int q    = htid & 3;          // kk within chunk (8 cols)
    const uint32_t dbase = sb + HB + (uint32_t)q * 2048u
                           + (uint32_t)(grow >> 4) * 512u
                           + (uint32_t)((grow >> 3) & 1) * 128u
                           + (uint32_t)(grow & 7) * 16u;

    const int tstride = 2 * gridDim.x;
    const int tile0   = 2 * blockIdx.x + halfid;

    // carried source pointers for this thread's row
    const float *cpx, *cphn, *cphd, *cphg;
    {
        const int gr0 = tile0 * TILE + grow;
        const int grc = (gr0 < M) ? ((gr0 < 0) ? 0 : gr0) : (M - 1);
        const int ci = stage_idx[grc];
        const int cb = batch[ci];
        int cg = 0;
        #pragma unroll 1
        while (cg + 1 < G && grc >= sCum[cg + 1]) cg++;
        cpx  = x  + (size_t)ci * 16;
        cphn = hn + (size_t)ci * 64;
        cphd = hd + (size_t)cb * 64;
        cphg = hg + (size_t)cg * 64;
    }

    auto issue = [&](int c, const float* px, const float* phn,
                     const float* phd, const float* phg) {
        const int col0 = 32 * c + 8 * q;
        if (col0 < 208) {
            const float* p;
            if      (col0 < 16)  p = px  + col0;
            else if (col0 < 80)  p = phn + (col0 - 16);
            else if (col0 < 144) p = phd + (col0 - 80);
            else                 p = phg + (col0 - 144);
            const uint32_t d = dbase + (uint32_t)(c & 3) * 8192u;
            cp16(d,        p);
            cp16(d + 256u, p + 4);
        }
        cp_commit();
    };

    if (tile0 < ntiles) {
        issue(0, cpx, cphn, cphd, cphg);
        issue(1, cpx, cphn, cphd, cphg);
        issue(2, cpx, cphn, cphd, cphg);
    }

    for (int tile = tile0; tile < ntiles; tile += tstride) {
        int nidx = 0, ngr = 0;
        const int tn = tile + tstride;
        const bool hasnext = (tn < ntiles);

        float acc[2][4][4];
        #pragma unroll
        for (int a = 0; a < 2; a++)
            #pragma unroll
            for (int b = 0; b < 4; b++)
                #pragma unroll
                for (int w = 0; w < 4; w++) acc[a][b][w] = 0.f;

        // ---------------- layer 1: 7 chunks, 4-buffer ring, 1 barrier/chunk --
        #pragma unroll
        for (int c = 0; c < NCH; c++) {
            if      (c <= 4) cp_wait<2>();
            else if (c == 5) cp_wait<1>();
            else             cp_wait<0>();
            hbar(barid);

            const char* ab = smem + HB + (c & 3) * 8192;
            const int kkmax = (c == NCH - 1) ? 2 : 4;
            #pragma unroll
            for (int kk = 0; kk < 4; kk++) {
                if (kk >= kkmax) break;
                uint32_t a[2][4];
                #pragma unroll
                for (int ml = 0; ml < 2; ml++) {
                    const uint32_t* ap =
                        (const uint32_t*)(ab + (kk * 4 + 2 * mg + ml) * 512) + lane;
                    a[ml][0] = ap[0];  a[ml][1] = ap[32];
                    a[ml][2] = ap[64]; a[ml][3] = ap[96];
                }
                const int kkg = 4 * c + kk;
                uint2 bf[4];
                #pragma unroll
                for (int nl = 0; nl < 4; nl++)
                    bf[nl] = ((const uint2*)(smem + SM_W1F))[(kkg * 16 + 4 * ng + nl) * 32 + lane];
                #pragma unroll
                for (int ml = 0; ml < 2; ml++)
                    #pragma unroll
                    for (int nl = 0; nl < 4; nl++)
                        mma_tf32(acc[ml][nl][0], acc[ml][nl][1], acc[ml][nl][2], acc[ml][nl][3],
                                 a[ml][0], a[ml][1], a[ml][2], a[ml][3],
                                 bf[nl].x, bf[nl].y);
            }
            if (c + 3 < NCH) issue(c + 3, cpx, cphn, cphd, cphg);
            if (c == 0) {
                const int te = hasnext ? tn : tile;
                const int g0 = te * TILE + grow;
                ngr  = (g0 < M) ? g0 : (M - 1);
                nidx = stage_idx[ngr];
            }
        }
        hbar(barid);   // all warps done reading A ring before H writes

        const int nbd = batch[nidx];

        // ---------------- epilogue 1: +b1, relu, tf32 -> H (fragment-major) --
        #pragma unroll
        for (int ml = 0; ml < 2; ml++) {
            #pragma unroll
            for (int nl = 0; nl < 4; nl++) {
                const int col0 = 32 * ng + 8 * nl + 2 * t4;
                const float2 bb = *(const float2*)(sB1 + col0);
                uint2 lo, hi;
                lo.x = f2tf(fmaxf(acc[ml][nl][0] + bb.x, 0.f));
                lo.y = f2tf(fmaxf(acc[ml][nl][1] + bb.y, 0.f));
                hi.x = f2tf(fmaxf(acc[ml][nl][2] + bb.x, 0.f));
                hi.y = f2tf(fmaxf(acc[ml][nl][3] + bb.y, 0.f));
                const int kk2 = 4 * ng + nl;
                const int m2  = 2 * mg + ml;
                const int reg = 2 * (t4 >> 1);
                const int ln2 = g4 * 4 + 2 * (t4 & 1);
                char* hp = smem + HB + ((kk2 * 4 + m2) * 4 + reg) * 128 + ln2 * 4;
                *(uint2*)(hp)       = lo;   // rows g4    (c0,c1)
                *(uint2*)(hp + 128) = hi;   // rows g4+8  (c2,c3)
            }
        }
        int ngg = 0;
        #pragma unroll 1
        while (ngg + 1 < G && ngr >= sCum[ngg + 1]) ngg++;
        hbar(barid);

        // ---------------- layer 2 ----------------
        float ac2[2][2][4];
        #pragma unroll
        for (int a = 0; a < 2; a++)
            #pragma unroll
            for (int b = 0; b < 2; b++)
                #pragma unroll
                for (int w = 0; w < 4; w++) ac2[a][b][w] = 0.f;

        #pragma unroll 4
        for (int kk = 0; kk < KK2; kk++) {
            uint32_t a[2][4];
            #pragma unroll
            for (int ml = 0; ml < 2; ml++) {
                const uint32_t* ap =
                    (const uint32_t*)(smem + HB + (kk * 4 + 2 * mg + ml) * 512) + lane;
                a[ml][0] = ap[0];  a[ml][1] = ap[32];
                a[ml][2] = ap[64]; a[ml][3] = ap[96];
            }
            uint2 bf[2];
            #pragma unroll
            for (int nl = 0; nl < 2; nl++)
                bf[nl] = ((const uint2*)(smem + SM_W2F))[(kk * 8 + 2 * ng + nl) * 32 + lane];
            #pragma unroll
            for (int ml = 0; ml < 2; ml++)
                #pragma unroll
                for (int nl = 0; nl < 2; nl++)
                    mma_tf32(ac2[ml][nl][0], ac2[ml][nl][1], ac2[ml][nl][2], ac2[ml][nl][3],
                             a[ml][0], a[ml][1], a[ml][2], a[ml][3],
                             bf[nl].x, bf[nl].y);
        }

        // ---------------- epilogue 2: +b2, relu, dot W3, reduce --------------
        #pragma unroll
        for (int ml = 0; ml < 2; ml++) {
            float p0 = 0.f, p1 = 0.f;
            #pragma unroll
            for (int nl = 0; nl < 2; nl++) {
                const int col0 = 16 * ng + 8 * nl + 2 * t4;
                const float2 bb = *(const float2*)(sB2 + col0);
                const float2 ww = *(const float2*)(sW3 + col0);
                p0 += fmaxf(ac2[ml][nl][0] + bb.x, 0.f) * ww.x
                    + fmaxf(ac2[ml][nl][1] + bb.y, 0.f) * ww.y;
                p1 += fmaxf(ac2[ml][nl][2] + bb.x, 0.f) * ww.x
                    + fmaxf(ac2[ml][nl][3] + bb.y, 0.f) * ww.y;
            }
            p0 += __shfl_xor_sync(0xffffffffu, p0, 1);
            p0 += __shfl_xor_sync(0xffffffffu, p0, 2);
            p1 += __shfl_xor_sync(0xffffffffu, p1, 1);
            p1 += __shfl_xor_sync(0xffffffffu, p1, 2);
            if (t4 == 0) {
                const int r0 = 32 * mg + 16 * ml + g4;
                sPt[r0 * 4 + ng]       = p0;
                sPt[(r0 + 8) * 4 + ng] = p1;
            }
        }
        hbar(barid);

        // out write + carry + cross-tile issues (H fully dead now)
        const int nbidx2 = nidx;
        cpx  = x  + (size_t)nbidx2 * 16;
        cphn = hn + (size_t)nbidx2 * 64;
        cphd = hd + (size_t)nbd * 64;
        cphg = hg + (size_t)ngg * 64;
        if (hasnext) {
            issue(0, cpx, cphn, cphd, cphg);
            issue(1, cpx, cphn, cphd, cphg);
            issue(2, cpx, cphn, cphd, cphg);
        }
        if (htid < 64) {
            const float4 p = ((const float4*)sPt)[htid];
            const int go = tile * TILE + htid;
            if (go < M) out[go] = p.x + p.y + p.z + p.w + b3v;
        }
    }
}

// ---------------------------------------------------------------------------
extern "C" void kernel_launch(void* const* d_in, const int* in_sizes, int n_in,
                              void* d_out, int out_size) {
    const float* x   = (const float*)d_in[0];
    const float* hn  = (const float*)d_in[1];
    const float* hd  = (const float*)d_in[2];
    const float* hg  = (const float*)d_in[3];
    const float* W1  = (const float*)d_in[4];
    const float* b1  = (const float*)d_in[5];
    const float* W2  = (const float*)d_in[6];
    const float* b2  = (const float*)d_in[7];
    const float* W3  = (const float*)d_in[8];
    const float* b3  = (const float*)d_in[9];
    const int* sidx  = (const int*)d_in[10];
    const int* batch = (const int*)d_in[11];
    const int* nsa   = (const int*)d_in[12];
    float* out = (float*)d_out;

    const int M = in_sizes[10];
    const int G = in_sizes[12];
    const int ntiles = (M + TILE - 1) / TILE;

    static int sms = 0;
    if (sms == 0) {
        cudaDeviceGetAttribute(&sms, cudaDevAttrMultiProcessorCount, 0);
        cudaFuncSetAttribute(stage_policy_kernel,
                             cudaFuncAttributeMaxDynamicSharedMemorySize, SMEM_TOTAL);
        if (sms <= 0) sms = 148;
    }
    const int half_tiles = (ntiles + 1) / 2;
    const int grid = (half_tiles < sms) ? half_tiles : sms;

    stage_policy_kernel<<<grid, 512, SMEM_TOTAL>>>(
        x, hn, hd, hg, W1, b1, W2, b2, W3, b3, sidx, batch, nsa, out, M, G, ntiles);
}

// round 10
// speedup vs baseline: 5.9854x; 5.9162x over previous
#include <cuda_runtime.h>
#include <cuda_fp16.h>
#include <cstdint>

// ============================================================================
// StagePolicyNetwork: gather -> [208x128] GEMM -> relu -> [128x64] GEMM
// -> relu -> [64x1] dot.  fp16 m16n8k16 mma.sync (fp32 accum) to halve the
// MMA instruction count (sm_103 fallback HMMA is per-instruction bound at
// ~fp32-FFMA rate). Persistent CTAs, 512 threads, 128-row tiles.
// compute_103-safe (no tcgen05).
// ============================================================================

__device__ __forceinline__ uint32_t pack_h2(float a, float b) {
    __half2 h = __floats2half2_rn(a, b);
    return *reinterpret_cast<uint32_t*>(&h);
}
__device__ __forceinline__ void mma_f16(float& c0, float& c1, float& c2, float& c3,
                                        uint32_t a0, uint32_t a1, uint32_t a2, uint32_t a3,
                                        uint32_t b0, uint32_t b1) {
    asm volatile(
        "mma.sync.aligned.m16n8k16.row.col.f32.f16.f16.f32 "
        "{%0,%1,%2,%3}, {%4,%5,%6,%7}, {%8,%9}, {%0,%1,%2,%3};"
        : "+f"(c0), "+f"(c1), "+f"(c2), "+f"(c3)
        : "r"(a0), "r"(a1), "r"(a2), "r"(a3), "r"(b0), "r"(b1));
}

// ---------------- constants --------------------------------------------------
static constexpr int TILE = 128;
static constexpr int KS1 = 13;          // 208 / 16 k-steps, layer 1
static constexpr int KS2 = 8;           // 128 / 16 k-steps, layer 2
static constexpr int RSTRIDE = 48;      // bytes per row (32B data + 16B pad)

// SMEM layout (bytes)
static constexpr int SM_W1F  = 0;                      // 13*16*32*8 = 53248
static constexpr int SM_W2F  = 53248;                  // 8*8*32*8   = 16384
static constexpr int SM_A    = 69632;                  // 13*128*48  = 79872
static constexpr int SM_H    = 149504;                 // 8*128*48   = 49152
static constexpr int SM_B1   = 198656;                 // 512
static constexpr int SM_B2   = 199168;                 // 256
static constexpr int SM_W3   = 199424;                 // 256
static constexpr int SM_PART = 199680;                 // 128*4*4 = 2048
static constexpr int SM_CUM  = 201728;                 // 80
static constexpr int SMEM_TOTAL = 201856;

__global__ __launch_bounds__(512, 1)
void stage_policy_kernel(
    const float* __restrict__ x, const float* __restrict__ hn,
    const float* __restrict__ hd, const float* __restrict__ hg,
    const float* __restrict__ W1g, const float* __restrict__ b1g,
    const float* __restrict__ W2g, const float* __restrict__ b2g,
    const float* __restrict__ W3g, const float* __restrict__ b3g,
    const int* __restrict__ stage_idx, const int* __restrict__ batch,
    const int* __restrict__ nsa,
    float* __restrict__ out, int M, int G, int ntiles)
{
    extern __shared__ char smem[];
    const int tid  = threadIdx.x;
    const int lane = tid & 31;
    const int g4   = lane >> 2;     // row within 8 / B col
    const int t4   = lane & 3;      // k pair
    const int wid  = tid >> 5;
    const int mg   = wid >> 2;      // rows 32*mg .. +32
    const int ng   = wid & 3;       // L1 cols 32*ng, L2 cols 16*ng

    float* sB1  = (float*)(smem + SM_B1);
    float* sB2  = (float*)(smem + SM_B2);
    float* sW3  = (float*)(smem + SM_W3);
    float* sPt  = (float*)(smem + SM_PART);
    int*   sCum = (int*)(smem + SM_CUM);

    // ---------------- one-time fills ----------------
    // W1 fragment-major fp16: [s(13)][nblk(16)][lane(32)] x {b0,b1}
    for (int i = tid; i < KS1 * 16 * 32; i += 512) {
        const int l = i & 31, n = (i >> 5) & 15, s = i >> 9;
        const int k0 = 16 * s + 2 * (l & 3);
        const int col = 8 * n + (l >> 2);
        uint2 v;
        v.x = pack_h2(W1g[k0 * 128 + col],       W1g[(k0 + 1) * 128 + col]);
        v.y = pack_h2(W1g[(k0 + 8) * 128 + col], W1g[(k0 + 9) * 128 + col]);
        ((uint2*)(smem + SM_W1F))[i] = v;
    }
    // W2 fragment-major fp16: [s(8)][nblk(8)][lane(32)] x {b0,b1}
    for (int i = tid; i < KS2 * 8 * 32; i += 512) {
        const int l = i & 31, n = (i >> 5) & 7, s = i >> 8;
        const int k0 = 16 * s + 2 * (l & 3);
        const int col = 8 * n + (l >> 2);
        uint2 v;
        v.x = pack_h2(W2g[k0 * 64 + col],       W2g[(k0 + 1) * 64 + col]);
        v.y = pack_h2(W2g[(k0 + 8) * 64 + col], W2g[(k0 + 9) * 64 + col]);
        ((uint2*)(smem + SM_W2F))[i] = v;
    }
    if (tid < 128) sB1[tid] = b1g[tid];
    if (tid >= 128 && tid < 192) sB2[tid - 128] = b2g[tid - 128];
    if (tid >= 192 && tid < 256) sW3[tid - 192] = W3g[tid - 192];
    if (tid == 0) {
        int c = 0; sCum[0] = 0;
        for (int i = 0; i < G; i++) { c += nsa[i]; sCum[i + 1] = c; }
    }
    const float b3v = b3g[0];
    __syncthreads();

    // gather role: 4 threads per row; each thread covers 4 cols of each k-step
    const int grow = tid >> 2;      // 0..127
    const int q    = tid & 3;       // float4 within k-step

    // carried per-tile gather state (prefetched one tile ahead)
    int cidx, cbd, cgg;
    {
        const int gr0 = blockIdx.x * TILE + grow;
        const int grc = (gr0 < M) ? gr0 : (M - 1);
        cidx = stage_idx[grc];
        cbd  = batch[cidx];
        int g = 0;
        #pragma unroll 1
        while (g + 1 < G && grc >= sCum[g + 1]) g++;
        cgg = g;
    }

    for (int tile = blockIdx.x; tile < ntiles; tile += gridDim.x) {
        const float* px  = x  + (size_t)cidx * 16;
        const float* phn = hn + (size_t)cidx * 64;
        const float* phd = hd + (size_t)cbd  * 64;
        const float* phg = hg + (size_t)cgg  * 64;

        // ---- gather: 13 LDG.128 -> fp16 -> STS.64 into SM_A ----
        char* arow = smem + SM_A + grow * RSTRIDE + q * 8;
        #pragma unroll
        for (int j = 0; j < KS1; j++) {
            const int col = 16 * j + 4 * q;
            const float* p;
            if      (col < 16)  p = px  + col;
            else if (col < 80)  p = phn + (col - 16);
            else if (col < 144) p = phd + (col - 80);
            else                p = phg + (col - 144);
            const float4 v = *(const float4*)p;
            uint2 h;
            h.x = pack_h2(v.x, v.y);
            h.y = pack_h2(v.z, v.w);
            *(uint2*)(arow + j * (128 * RSTRIDE)) = h;
        }

        // prefetch next tile's indices (hidden under MMA phase)
        int nidx, nbd, ngg;
        {
            const int tn  = tile + gridDim.x;
            const int g0  = tn * TILE + grow;
            const int grn = (tn < ntiles) ? ((g0 < M) ? g0 : (M - 1)) : 0;
            nidx = stage_idx[grn];
            nbd  = batch[nidx];
            int g = 0;
            #pragma unroll 1
            while (g + 1 < G && grn >= sCum[g + 1]) g++;
            ngg = g;
        }
        __syncthreads();   // bar 1: A ready

        // ---------------- layer 1: 13 k-steps of m16n8k16 ----------------
        float acc[2][4][4];
        #pragma unroll
        for (int a = 0; a < 2; a++)
            #pragma unroll
            for (int b = 0; b < 4; b++)
                #pragma unroll
                for (int w = 0; w < 4; w++) acc[a][b][w] = 0.f;

        #pragma unroll
        for (int s = 0; s < KS1; s++) {
            uint32_t a[2][4];
            #pragma unroll
            for (int ml = 0; ml < 2; ml++) {
                const char* ap = smem + SM_A + s * (128 * RSTRIDE)
                                 + (32 * mg + 16 * ml + g4) * RSTRIDE + t4 * 4;
                a[ml][0] = *(const uint32_t*)(ap);
                a[ml][1] = *(const uint32_t*)(ap + 8 * RSTRIDE);
                a[ml][2] = *(const uint32_t*)(ap + 16);
                a[ml][3] = *(const uint32_t*)(ap + 8 * RSTRIDE + 16);
            }
            uint2 bf[4];
            #pragma unroll
            for (int nl = 0; nl < 4; nl++)
                bf[nl] = ((const uint2*)(smem + SM_W1F))[(s * 16 + 4 * ng + nl) * 32 + lane];
            #pragma unroll
            for (int ml = 0; ml < 2; ml++)
                #pragma unroll
                for (int nl = 0; nl < 4; nl++)
                    mma_f16(acc[ml][nl][0], acc[ml][nl][1], acc[ml][nl][2], acc[ml][nl][3],
                            a[ml][0], a[ml][1], a[ml][2], a[ml][3],
                            bf[nl].x, bf[nl].y);
        }

        // ---- epilogue 1: +b1, relu, fp16 -> SM_H ----
        #pragma unroll
        for (int ml = 0; ml < 2; ml++) {
            #pragma unroll
            for (int nl = 0; nl < 4; nl++) {
                const int col0 = 32 * ng + 8 * nl + 2 * t4;
                const float2 bb = *(const float2*)(sB1 + col0);
                const uint32_t lo = pack_h2(fmaxf(acc[ml][nl][0] + bb.x, 0.f),
                                            fmaxf(acc[ml][nl][1] + bb.y, 0.f));
                const uint32_t hi = pack_h2(fmaxf(acc[ml][nl][2] + bb.x, 0.f),
                                            fmaxf(acc[ml][nl][3] + bb.y, 0.f));
                const int s2   = col0 >> 4;                  // k-step in layer 2
                const int kin  = col0 & 15;                  // k within step
                const int r0   = 32 * mg + 16 * ml + g4;
                char* hp = smem + SM_H + s2 * (128 * RSTRIDE) + r0 * RSTRIDE + kin * 2;
                *(uint32_t*)(hp)                = lo;        // rows r0
                *(uint32_t*)(hp + 8 * RSTRIDE)  = hi;        // rows r0+8
            }
        }
        __syncthreads();   // bar 2: H ready

        // ---------------- layer 2: 8 k-steps ----------------
        float ac2[2][2][4];
        #pragma unroll
        for (int a = 0; a < 2; a++)
            #pragma unroll
            for (int b = 0; b < 2; b++)
                #pragma unroll
                for (int w = 0; w < 4; w++) ac2[a][b][w] = 0.f;

        #pragma unroll
        for (int s = 0; s < KS2; s++) {
            uint32_t a[2][4];
            #pragma unroll
            for (int ml = 0; ml < 2; ml++) {
                const char* ap = smem + SM_H + s * (128 * RSTRIDE)
                                 + (32 * mg + 16 * ml + g4) * RSTRIDE + t4 * 4;
                a[ml][0] = *(const uint32_t*)(ap);
                a[ml][1] = *(const uint32_t*)(ap + 8 * RSTRIDE);
                a[ml][2] = *(const uint32_t*)(ap + 16);
                a[ml][3] = *(const uint32_t*)(ap + 8 * RSTRIDE + 16);
            }
            uint2 bf[2];
            #pragma unroll
            for (int nl = 0; nl < 2; nl++)
                bf[nl] = ((const uint2*)(smem + SM_W2F))[(s * 8 + 2 * ng + nl) * 32 + lane];
            #pragma unroll
            for (int ml = 0; ml < 2; ml++)
                #pragma unroll
                for (int nl = 0; nl < 2; nl++)
                    mma_f16(ac2[ml][nl][0], ac2[ml][nl][1], ac2[ml][nl][2], ac2[ml][nl][3],
                            a[ml][0], a[ml][1], a[ml][2], a[ml][3],
                            bf[nl].x, bf[nl].y);
        }

        // ---- epilogue 2: +b2, relu, dot W3, reduce ----
        #pragma unroll
        for (int ml = 0; ml < 2; ml++) {
            float p0 = 0.f, p1 = 0.f;
            #pragma unroll
            for (int nl = 0; nl < 2; nl++) {
                const int col0 = 16 * ng + 8 * nl + 2 * t4;
                const float2 bb = *(const float2*)(sB2 + col0);
                const float2 ww = *(const float2*)(sW3 + col0);
                p0 += fmaxf(ac2[ml][nl][0] + bb.x, 0.f) * ww.x
                    + fmaxf(ac2[ml][nl][1] + bb.y, 0.f) * ww.y;
                p1 += fmaxf(ac2[ml][nl][2] + bb.x, 0.f) * ww.x
                    + fmaxf(ac2[ml][nl][3] + bb.y, 0.f) * ww.y;
            }
            p0 += __shfl_xor_sync(0xffffffffu, p0, 1);
            p0 += __shfl_xor_sync(0xffffffffu, p0, 2);
            p1 += __shfl_xor_sync(0xffffffffu, p1, 1);
            p1 += __shfl_xor_sync(0xffffffffu, p1, 2);
            if (t4 == 0) {
                const int r0 = 32 * mg + 16 * ml + g4;
                sPt[r0 * 4 + ng]       = p0;
                sPt[(r0 + 8) * 4 + ng] = p1;
            }
        }
        __syncthreads();   // bar 3: partials ready

        if (tid < 128) {
            const float4 p = ((const float4*)sPt)[tid];
            const int go = tile * TILE + tid;
            if (go < M) out[go] = p.x + p.y + p.z + p.w + b3v;
        }

        cidx = nidx; cbd = nbd; cgg = ngg;
    }
}

// ---------------------------------------------------------------------------
extern "C" void kernel_launch(void* const* d_in, const int* in_sizes, int n_in,
                              void* d_out, int out_size) {
    const float* x   = (const float*)d_in[0];
    const float* hn  = (const float*)d_in[1];
    const float* hd  = (const float*)d_in[2];
    const float* hg  = (const float*)d_in[3];
    const float* W1  = (const float*)d_in[4];
    const float* b1  = (const float*)d_in[5];
    const float* W2  = (const float*)d_in[6];
    const float* b2  = (const float*)d_in[7];
    const float* W3  = (const float*)d_in[8];
    const float* b3  = (const float*)d_in[9];
    const int* sidx  = (const int*)d_in[10];
    const int* batch = (const int*)d_in[11];
    const int* nsa   = (const int*)d_in[12];
    float* out = (float*)d_out;

    const int M = in_sizes[10];
    const int G = in_sizes[12];
    const int ntiles = (M + TILE - 1) / TILE;

    static int sms = 0;
    if (sms == 0) {
        cudaDeviceGetAttribute(&sms, cudaDevAttrMultiProcessorCount, 0);
        cudaFuncSetAttribute(stage_policy_kernel,
                             cudaFuncAttributeMaxDynamicSharedMemorySize, SMEM_TOTAL);
        if (sms <= 0) sms = 148;
    }
    const int grid = (ntiles < sms) ? ntiles : sms;

    stage_policy_kernel<<<grid, 512, SMEM_TOTAL>>>(
        x, hn, hd, hg, W1, b1, W2, b2, W3, b3, sidx, batch, nsa, out, M, G, ntiles);
}